// round 14
// baseline (speedup 1.0000x reference)
#include <cuda_runtime.h>
#include <cuda_fp16.h>
#include <cstdint>

#define BB 4
#define SS 2048
#define EE 1024
#define HH 16
#define DD 64
#define FF 4096
#define LN_EPS 1e-5f
#define NTOK (BB*SS)
#define HTOK (NTOK/2)
#define EXP_SHIFT 12.0f

// ---------------- scratch (device globals) ----------------
__device__ __half g_Xh[(long)NTOK*EE];
__device__ __half g_Wqk[2048L*EE];
__device__ __half g_Wvt[1024L*EE];
__device__ __half g_Wot[1024L*1024];
__device__ __half g_W1t[(long)FF*EE];
__device__ __half g_W2t[(long)EE*FF];
__device__ __half g_QKh[(long)NTOK*2048];
__device__ __half g_Vth[(long)BB*1024*SS];
__device__ __half g_att[268435456L];
__device__ float  g_part[64L*32*SS];
__device__ float  g_inv[(long)BB*HH*SS];
__device__ __half g_AVh[(long)NTOK*EE];
__device__ float  g_Y[(long)NTOK*EE];
__device__ float  g_VAf[(long)NTOK*EE];
__device__ __half g_VAh[(long)NTOK*EE];
__device__ __half g_H1h[(long)NTOK*FF];
__device__ float  g_Z[(long)NTOK*EE];

// ---------------- PTX helpers ----------------
__device__ __forceinline__ uint32_t smem_u32(const void* p) {
    uint32_t a;
    asm("{ .reg .u64 t; cvta.to.shared.u64 t, %1; cvt.u32.u64 %0, t; }" : "=r"(a) : "l"(p));
    return a;
}
__device__ __forceinline__ void cp16(uint32_t dst, const void* src) {
    asm volatile("cp.async.cg.shared.global [%0], [%1], 16;" :: "r"(dst), "l"(src));
}

// ---------------- HMMA f16 GEMM: C[M,N] = A[M,K] * B[N,K]^T ----------------
// BM=128, BK=64, 128 threads = 4 warps (2m x 2n), warp 64xWN.
// 3-stage cp.async pipeline; fragment double-buffering across ks steps.
template<int BN, bool OUT_HALF>
__global__ __launch_bounds__(128, 2)
void hgemm_kernel(const __half* __restrict__ A, const __half* __restrict__ B,
                  void* __restrict__ Cv, int K, int lda, int ldb, int ldc,
                  long sA1, long sA2, long sB1, long sB2, long sC1, long sC2, int Z2,
                  const float* __restrict__ bias, const float* __restrict__ residual,
                  int ldr, int do_relu, int do_exp, float* __restrict__ part)
{
    constexpr int BM = 128;
    constexpr int STG_A = BM * 128;
    constexpr int STG_B = BN * 128;
    constexpr int STG   = STG_A + STG_B;
    constexpr int WN = BN / 2;
    constexpr int MT = 4;
    constexpr int NT = WN / 8;

    extern __shared__ char smem_raw[];
    const uint32_t sb0   = smem_u32(smem_raw);
    const uint32_t sbase = (sb0 + 127u) & ~127u;

    const int tid  = threadIdx.x;
    const int lane = tid & 31;
    const int wid  = tid >> 5;
    const int wm   = (wid & 1) << 6;
    const int wn   = (wid >> 1) * WN;

    const int z  = blockIdx.z;
    const int z1 = z / Z2, z2 = z - z1 * Z2;
    A += z1 * sA1 + z2 * sA2;
    B += z1 * sB1 + z2 * sB2;
    const long coff = z1 * sC1 + z2 * sC2;
    const int m0 = blockIdx.y * BM;
    const int n0 = blockIdx.x * BN;

    float acc[MT][NT][4];
    #pragma unroll
    for (int i = 0; i < MT; i++)
        #pragma unroll
        for (int j = 0; j < NT; j++)
            #pragma unroll
            for (int k = 0; k < 4; k++) acc[i][j][k] = 0.0f;

    const int nK = K >> 6;

    auto load_stage = [&](int stg, int kt) {
        uint32_t sA = sbase + stg * STG;
        const char* Ab = (const char*)(A + (long)m0 * lda + kt * 64);
        #pragma unroll
        for (int idx = tid; idx < BM * 8; idx += 128) {
            int r = idx >> 3, c = (idx & 7) << 4;
            uint32_t off = (uint32_t)(r * 128 + c); off ^= (off >> 3) & 0x70;
            cp16(sA + off, Ab + (long)r * lda * 2 + c);
        }
        uint32_t sB = sbase + stg * STG + STG_A;
        const char* Bb = (const char*)(B + (long)n0 * ldb + kt * 64);
        #pragma unroll
        for (int idx = tid; idx < BN * 8; idx += 128) {
            int r = idx >> 3, c = (idx & 7) << 4;
            uint32_t off = (uint32_t)(r * 128 + c); off ^= (off >> 3) & 0x70;
            cp16(sB + off, Bb + (long)r * ldb * 2 + c);
        }
        asm volatile("cp.async.commit_group;" ::: "memory");
    };

    uint32_t afrag[2][MT][4];
    uint32_t bfrag[2][NT][2];
    auto load_afrags = [&](uint32_t sA, int ks, int buf) {
        #pragma unroll
        for (int mt = 0; mt < MT; mt++) {
            int m = wm + (mt << 4) + (lane & 15);
            uint32_t off = (uint32_t)((m << 7) + (ks << 5) + ((lane >> 4) << 4));
            off ^= (off >> 3) & 0x70;
            asm volatile("ldmatrix.sync.aligned.m8n8.x4.shared.b16 {%0,%1,%2,%3}, [%4];"
                : "=r"(afrag[buf][mt][0]), "=r"(afrag[buf][mt][1]),
                  "=r"(afrag[buf][mt][2]), "=r"(afrag[buf][mt][3])
                : "r"(sA + off));
        }
    };
    auto load_bfrags = [&](uint32_t sB, int ks, int buf) {
        #pragma unroll
        for (int p = 0; p < NT / 2; p++) {
            int quad = lane >> 3;
            int n = wn + (p << 4) + ((quad & 2) << 2) + (lane & 7);
            uint32_t off = (uint32_t)((n << 7) + (ks << 5) + ((quad & 1) << 4));
            off ^= (off >> 3) & 0x70;
            asm volatile("ldmatrix.sync.aligned.m8n8.x4.shared.b16 {%0,%1,%2,%3}, [%4];"
                : "=r"(bfrag[buf][2*p][0]), "=r"(bfrag[buf][2*p][1]),
                  "=r"(bfrag[buf][2*p+1][0]), "=r"(bfrag[buf][2*p+1][1])
                : "r"(sB + off));
        }
    };
    auto mma_all = [&](int buf) {
        #pragma unroll
        for (int mt = 0; mt < MT; mt++)
            #pragma unroll
            for (int nt = 0; nt < NT; nt++)
                asm("mma.sync.aligned.m16n8k16.row.col.f32.f16.f16.f32 "
                    "{%0,%1,%2,%3}, {%4,%5,%6,%7}, {%8,%9}, {%0,%1,%2,%3};"
                    : "+f"(acc[mt][nt][0]), "+f"(acc[mt][nt][1]),
                      "+f"(acc[mt][nt][2]), "+f"(acc[mt][nt][3])
                    : "r"(afrag[buf][mt][0]), "r"(afrag[buf][mt][1]),
                      "r"(afrag[buf][mt][2]), "r"(afrag[buf][mt][3]),
                      "r"(bfrag[buf][nt][0]), "r"(bfrag[buf][nt][1]));
    };

    load_stage(0, 0);
    if (nK > 1) load_stage(1, 1);

    for (int i = 0; i < nK; i++) {
        if (i + 1 < nK) asm volatile("cp.async.wait_group 1;" ::: "memory");
        else            asm volatile("cp.async.wait_group 0;" ::: "memory");
        __syncthreads();
        if (i + 2 < nK) load_stage((i + 2) % 3, i + 2);

        const uint32_t sA = sbase + (i % 3) * STG;
        const uint32_t sB = sA + STG_A;

        load_afrags(sA, 0, 0);
        load_bfrags(sB, 0, 0);
        #pragma unroll
        for (int ks = 0; ks < 4; ks++) {
            if (ks < 3) {
                load_afrags(sA, ks + 1, (ks + 1) & 1);
                load_bfrags(sB, ks + 1, (ks + 1) & 1);
            }
            mma_all(ks & 1);
        }
    }

    // -------- epilogue --------
    const int mrow = lane >> 2;
    const int ncol = (lane & 3) << 1;
    float cs[NT][2];
    #pragma unroll
    for (int j = 0; j < NT; j++) { cs[j][0] = 0.0f; cs[j][1] = 0.0f; }

    #pragma unroll
    for (int mt = 0; mt < MT; mt++) {
        #pragma unroll
        for (int nt = 0; nt < NT; nt++) {
            long gm = m0 + wm + (mt << 4) + mrow;
            int  gn = n0 + wn + (nt << 3) + ncol;
            float v0 = acc[mt][nt][0], v1 = acc[mt][nt][1];
            float v2 = acc[mt][nt][2], v3 = acc[mt][nt][3];
            if (bias) {
                float b0 = bias[gn], b1 = bias[gn + 1];
                v0 += b0; v1 += b1; v2 += b0; v3 += b1;
            }
            if (residual) {
                const float2 r0 = *(const float2*)(residual + gm * ldr + gn);
                const float2 r1 = *(const float2*)(residual + (gm + 8) * ldr + gn);
                v0 += r0.x; v1 += r0.y; v2 += r1.x; v3 += r1.y;
            }
            if (do_relu) {
                v0 = fmaxf(v0, 0.0f); v1 = fmaxf(v1, 0.0f);
                v2 = fmaxf(v2, 0.0f); v3 = fmaxf(v3, 0.0f);
            }
            if (do_exp) {
                v0 = fminf(__expf(v0 - EXP_SHIFT), 60000.0f);
                v1 = fminf(__expf(v1 - EXP_SHIFT), 60000.0f);
                v2 = fminf(__expf(v2 - EXP_SHIFT), 60000.0f);
                v3 = fminf(__expf(v3 - EXP_SHIFT), 60000.0f);
                cs[nt][0] += v0 + v2;
                cs[nt][1] += v1 + v3;
            }
            if (OUT_HALF) {
                *(__half2*)((__half*)Cv + coff + gm * ldc + gn)       = __floats2half2_rn(v0, v1);
                *(__half2*)((__half*)Cv + coff + (gm + 8) * ldc + gn) = __floats2half2_rn(v2, v3);
            } else {
                *(float2*)((float*)Cv + coff + gm * ldc + gn)       = make_float2(v0, v1);
                *(float2*)((float*)Cv + coff + (gm + 8) * ldc + gn) = make_float2(v2, v3);
            }
        }
    }

    if (do_exp) {
        #pragma unroll
        for (int nt = 0; nt < NT; nt++) {
            float c0 = cs[nt][0], c1 = cs[nt][1];
            #pragma unroll
            for (int o = 4; o <= 16; o <<= 1) {
                c0 += __shfl_xor_sync(0xffffffffu, c0, o);
                c1 += __shfl_xor_sync(0xffffffffu, c1, o);
            }
            if ((lane >> 2) == 0) {
                int gn = n0 + wn + (nt << 3) + ncol;
                long idx = (((long)z * gridDim.y + blockIdx.y) * 2 + (wid & 1)) * SS + gn;
                part[idx]     = c0;
                part[idx + 1] = c1;
            }
        }
    }
}

// ---------------- conversion / packing kernels ----------------
__global__ __launch_bounds__(256) void f2h_kernel(const float4* __restrict__ s,
                                                  __half2* __restrict__ d, long n4) {
    long i = (long)blockIdx.x * 256 + threadIdx.x;
    if (i < n4) {
        float4 v = s[i];
        d[i * 2]     = __floats2half2_rn(v.x, v.y);
        d[i * 2 + 1] = __floats2half2_rn(v.z, v.w);
    }
}
__global__ __launch_bounds__(256) void pack_w_kernel(const float* __restrict__ W,
                                                     __half* __restrict__ dst) {
    __shared__ float tile[32][33];
    int h  = blockIdx.z;
    int eb = blockIdx.y * 32, db = blockIdx.x * 32;
    const float* Wh = W + (long)h * EE * DD;
    #pragma unroll
    for (int dy = 0; dy < 32; dy += 8)
        tile[threadIdx.y + dy][threadIdx.x] =
            Wh[(long)(eb + threadIdx.y + dy) * DD + db + threadIdx.x];
    __syncthreads();
    #pragma unroll
    for (int dy = 0; dy < 32; dy += 8)
        dst[(long)(h * DD + db + threadIdx.y + dy) * EE + eb + threadIdx.x] =
            __float2half(tile[threadIdx.x][threadIdx.y + dy]);
}
__global__ __launch_bounds__(256) void transpose_h_kernel(const float* __restrict__ src,
                                                          __half* __restrict__ dst,
                                                          int R, int C) {
    __shared__ float tile[32][33];
    int rb = blockIdx.y * 32, cb = blockIdx.x * 32;
    #pragma unroll
    for (int dy = 0; dy < 32; dy += 8)
        tile[threadIdx.y + dy][threadIdx.x] =
            src[(long)(rb + threadIdx.y + dy) * C + cb + threadIdx.x];
    __syncthreads();
    #pragma unroll
    for (int dy = 0; dy < 32; dy += 8)
        dst[(long)(cb + threadIdx.y + dy) * R + rb + threadIdx.x] =
            __float2half(tile[threadIdx.x][threadIdx.y + dy]);
}

// ---------------- reduce partial col sums -> inv = 0.125/sum ----------------
__global__ __launch_bounds__(256) void reduce_inv_kernel(const float* __restrict__ part,
                                                         float* __restrict__ inv) {
    long z = blockIdx.y;
    int  t = blockIdx.x * 256 + threadIdx.x;
    const float* p = part + (z * 32) * (long)SS + t;
    float s = 0.0f;
    #pragma unroll
    for (int j = 0; j < 32; j++) s += p[(long)j * SS];
    inv[z * (long)SS + t] = 0.125f / s;
}

// ---------------- scale Vth rows by inv ----------------
__global__ __launch_bounds__(256) void vscale_kernel(__half* __restrict__ v,
                                                     const float* __restrict__ inv,
                                                     long nelem) {
    long i2 = (long)blockIdx.x * 256 + threadIdx.x;
    long i  = i2 * 2;
    if (i >= nelem) return;
    int t  = (int)(i & (SS - 1));
    int hd = (int)((i >> 11) & 1023);
    int b  = (int)(i >> 21);
    const float* ip = inv + ((long)(b * HH + (hd >> 6))) * SS + t;
    __half2* p = (__half2*)(v + i);
    float2 f = __half22float2(*p);
    f.x *= ip[0]; f.y *= ip[1];
    *p = __floats2half2_rn(f.x, f.y);
}

// ---------------- layernorm (E=1024), optional half copy ----------------
__global__ __launch_bounds__(256)
void layernorm_kernel(const float* __restrict__ x, const float* __restrict__ gamma,
                      const float* __restrict__ beta, float* __restrict__ outf,
                      __half* __restrict__ outh) {
    long row = blockIdx.x;
    const float* p = x + row * (long)EE;
    const int tid = threadIdx.x, lane = tid & 31, warp = tid >> 5;

    float v[4]; float s = 0.0f;
    #pragma unroll
    for (int i = 0; i < 4; i++) { v[i] = p[tid + i * 256]; s += v[i]; }
    __shared__ float red1[8], red2[8];
    #pragma unroll
    for (int o = 16; o > 0; o >>= 1) s += __shfl_xor_sync(0xffffffffu, s, o);
    if (lane == 0) red1[warp] = s;
    __syncthreads();
    float tot = red1[0];
    #pragma unroll
    for (int i = 1; i < 8; i++) tot += red1[i];
    float mu = tot * (1.0f / EE);

    float q = 0.0f;
    #pragma unroll
    for (int i = 0; i < 4; i++) { float d = v[i] - mu; q += d * d; }
    #pragma unroll
    for (int o = 16; o > 0; o >>= 1) q += __shfl_xor_sync(0xffffffffu, q, o);
    if (lane == 0) red2[warp] = q;
    __syncthreads();
    float qt = red2[0];
    #pragma unroll
    for (int i = 1; i < 8; i++) qt += red2[i];
    float rstd = rsqrtf(qt * (1.0f / EE) + LN_EPS);

    #pragma unroll
    for (int i = 0; i < 4; i++) {
        int col = tid + i * 256;
        float y = (v[i] - mu) * rstd * gamma[col] + beta[col];
        outf[row * (long)EE + col] = y;
        if (outh) outh[row * (long)EE + col] = __float2half(y);
    }
}

// ---------------- launcher ----------------
extern "C" void kernel_launch(void* const* d_in, const int* in_sizes, int n_in,
                              void* d_out, int out_size)
{
    const float* X     = (const float*)d_in[0];
    const float* WQ    = (const float*)d_in[1];
    const float* WK    = (const float*)d_in[2];
    const float* WV    = (const float*)d_in[3];
    const float* WO    = (const float*)d_in[4];
    const float* gamma = (const float*)d_in[5];
    const float* beta  = (const float*)d_in[6];
    const float* W1    = (const float*)d_in[7];
    const float* b1    = (const float*)d_in[8];
    const float* W2    = (const float*)d_in[9];
    const float* b2    = (const float*)d_in[10];
    float* out = (float*)d_out;

    __half *Xh, *Wqk, *Wvt, *Wot, *W1t, *W2t, *QKh, *Vth, *ATT, *AVh, *VAh, *H1h;
    float *PART, *INV, *Y, *VAf, *Z;
    cudaGetSymbolAddress((void**)&Xh,  g_Xh);
    cudaGetSymbolAddress((void**)&Wqk, g_Wqk);
    cudaGetSymbolAddress((void**)&Wvt, g_Wvt);
    cudaGetSymbolAddress((void**)&Wot, g_Wot);
    cudaGetSymbolAddress((void**)&W1t, g_W1t);
    cudaGetSymbolAddress((void**)&W2t, g_W2t);
    cudaGetSymbolAddress((void**)&QKh, g_QKh);
    cudaGetSymbolAddress((void**)&Vth, g_Vth);
    cudaGetSymbolAddress((void**)&ATT, g_att);
    cudaGetSymbolAddress((void**)&PART, g_part);
    cudaGetSymbolAddress((void**)&INV, g_inv);
    cudaGetSymbolAddress((void**)&AVh, g_AVh);
    cudaGetSymbolAddress((void**)&Y,   g_Y);
    cudaGetSymbolAddress((void**)&VAf, g_VAf);
    cudaGetSymbolAddress((void**)&VAh, g_VAh);
    cudaGetSymbolAddress((void**)&H1h, g_H1h);
    cudaGetSymbolAddress((void**)&Z,   g_Z);

    static cudaStream_t sW = nullptr, sH[2] = {nullptr, nullptr};
    static cudaEvent_t evFork = nullptr, evW = nullptr, evD0 = nullptr, evD1 = nullptr;
    if (!sW) {
        int pl, pg;
        cudaDeviceGetStreamPriorityRange(&pl, &pg);
        cudaStreamCreateWithFlags(&sW, cudaStreamNonBlocking);
        cudaStreamCreateWithPriority(&sH[0], cudaStreamNonBlocking, pg);   // high prio
        cudaStreamCreateWithPriority(&sH[1], cudaStreamNonBlocking, pl);   // low prio
        cudaEventCreateWithFlags(&evFork, cudaEventDisableTiming);
        cudaEventCreateWithFlags(&evW,    cudaEventDisableTiming);
        cudaEventCreateWithFlags(&evD0,   cudaEventDisableTiming);
        cudaEventCreateWithFlags(&evD1,   cudaEventDisableTiming);
    }

    const int SM128 = 3 * (128 * 128 + 128 * 128) + 256;
    const int SM64  = 3 * (128 * 128 +  64 * 128) + 256;
    cudaFuncSetAttribute(hgemm_kernel<128, true>,  cudaFuncAttributeMaxDynamicSharedMemorySize, SM128);
    cudaFuncSetAttribute(hgemm_kernel<128, false>, cudaFuncAttributeMaxDynamicSharedMemorySize, SM128);
    cudaFuncSetAttribute(hgemm_kernel<64,  true>,  cudaFuncAttributeMaxDynamicSharedMemorySize, SM64);

    const long SSl = SS, SSS = SSl * SSl;
    dim3 blk(256);
    dim3 gblk(128);
    dim3 tblk(32, 8);

    // ---- stream 0: shared prep (Xh + QK weight pack), then fork ----
    f2h_kernel<<<(NTOK * (long)EE / 4 + 255) / 256, blk>>>(
        (const float4*)X, (__half2*)Xh, NTOK * (long)EE / 4);
    pack_w_kernel<<<dim3(2, 32, HH), tblk>>>(WQ, Wqk);
    pack_w_kernel<<<dim3(2, 32, HH), tblk>>>(WK, Wqk + 1024L * EE);
    cudaEventRecord(evFork, 0);

    // ---- weight stream: V/O/FFN weight packs (independent of X) ----
    cudaStreamWaitEvent(sW, evFork, 0);
    pack_w_kernel<<<dim3(2, 32, HH), tblk, 0, sW>>>(WV, Wvt);
    transpose_h_kernel<<<dim3(1024 / 32, 1024 / 32), tblk, 0, sW>>>(WO, Wot, 1024, 1024);
    transpose_h_kernel<<<dim3(FF / 32, EE / 32), tblk, 0, sW>>>(W1, W1t, EE, FF);
    transpose_h_kernel<<<dim3(EE / 32, FF / 32), tblk, 0, sW>>>(W2, W2t, FF, EE);
    cudaEventRecord(evW, sW);

    // ---- per-half pipelines (h = 0: batches 0-1, h = 1: batches 2-3) ----
    for (int h = 0; h < 2; h++) {
        cudaStream_t s = sH[h];
        cudaStreamWaitEvent(s, evFork, 0);
        cudaStreamWaitEvent(s, evW, 0);

        const long xOff   = (long)h * HTOK * EE;       // tokens (fp32/half X, AV, Y, VA, Z, out)
        const long qkOff  = (long)h * HTOK * 2048;
        const long vtOff  = (long)h * 2 * 1024L * SS;
        const long attOff = (long)h * 32L * SSS;
        const long partOff= (long)h * 32L * 32 * SS;
        const long invOff = (long)h * 32L * SS;
        const long h1Off  = (long)h * HTOK * (long)FF;

        // 1) QK projection half: [4096,1024] x [2048,1024]^T -> QKh
        hgemm_kernel<128, true><<<dim3(2048 / 128, HTOK / 128, 1), gblk, SM128, s>>>(
            Xh + xOff, Wqk, QKh + qkOff, EE, EE, EE, 2048,
            0, 0, 0, 0, 0, 0, 1, nullptr, nullptr, 0, 0, 0, nullptr);

        // 2) Vt half: per b: Wvt [1024,1024] x Xh_b^T -> Vth[b][1024,2048]
        hgemm_kernel<128, true><<<dim3(SS / 128, 1024 / 128, 2), gblk, SM128, s>>>(
            Wvt, Xh + xOff, Vth + vtOff, EE, EE, EE, SS,
            0, 0, (long)SS * EE, 0, 1024L * SS, 0, 1, nullptr, nullptr, 0, 0, 0, nullptr);

        // 3) scores + exp + partial col sums (32 z per half)
        hgemm_kernel<128, true><<<dim3(SS / 128, SS / 128, 2 * HH), gblk, SM128, s>>>(
            QKh + qkOff, QKh + qkOff + 1024, ATT + attOff, DD, 2048, 2048, SS,
            SSl * 2048, 64, SSl * 2048, 64, (long)HH * SSS, SSS, HH,
            nullptr, nullptr, 0, 0, 1, PART + partOff);

        // 4) reduce partials -> inv; fold into V
        reduce_inv_kernel<<<dim3(SS / 256, 2 * HH), blk, 0, s>>>(PART + partOff, INV + invOff);
        vscale_kernel<<<(int)((2 * 1024L * SS / 2 + 255) / 256), blk, 0, s>>>(
            Vth + vtOff, INV + invOff, 2 * 1024L * SS);

        // 5) AV half
        hgemm_kernel<64, true><<<dim3(1, SS / 128, 2 * HH), gblk, SM64, s>>>(
            ATT + attOff, Vth + vtOff, AVh + xOff, SS, SS, SS, EE,
            (long)HH * SSS, SSS, 1024L * SS, 64L * SS, SSl * EE, 64, HH,
            nullptr, nullptr, 0, 0, 0, nullptr);

        // 6) WO + residual X; LN -> VAf/VAh
        hgemm_kernel<128, false><<<dim3(EE / 128, HTOK / 128, 1), gblk, SM128, s>>>(
            AVh + xOff, Wot, Y + xOff, 1024, 1024, 1024, EE,
            0, 0, 0, 0, 0, 0, 1, nullptr, X + xOff, EE, 0, 0, nullptr);
        layernorm_kernel<<<HTOK, blk, 0, s>>>(Y + xOff, gamma, beta, VAf + xOff, VAh + xOff);

        // 7) FFN1
        hgemm_kernel<128, true><<<dim3(FF / 128, HTOK / 128, 1), gblk, SM128, s>>>(
            VAh + xOff, W1t, H1h + h1Off, EE, EE, EE, FF,
            0, 0, 0, 0, 0, 0, 1, b1, nullptr, 0, 1, 0, nullptr);

        // 8) FFN2 + residual VAf; LN -> out
        hgemm_kernel<128, false><<<dim3(EE / 128, HTOK / 128, 1), gblk, SM128, s>>>(
            H1h + h1Off, W2t, Z + xOff, FF, FF, FF, EE,
            0, 0, 0, 0, 0, 0, 1, b2, VAf + xOff, EE, 0, 0, nullptr);
        layernorm_kernel<<<HTOK, blk, 0, s>>>(Z + xOff, gamma, beta, out + xOff, nullptr);

        cudaEventRecord(h == 0 ? evD0 : evD1, s);
    }

    // ---- join back to capture stream ----
    cudaStreamWaitEvent(0, evD0, 0);
    cudaStreamWaitEvent(0, evD1, 0);
}

// round 15
// speedup vs baseline: 1.0021x; 1.0021x over previous
#include <cuda_runtime.h>
#include <cuda_fp16.h>
#include <cstdint>

#define BB 4
#define SS 2048
#define EE 1024
#define HH 16
#define DD 64
#define FF 4096
#define LN_EPS 1e-5f
#define NTOK (BB*SS)
#define HTOK (NTOK/2)
#define EXP_SHIFT 12.0f

// ---------------- scratch (device globals) ----------------
__device__ __half g_Xh[(long)NTOK*EE];
__device__ __half g_Wqk[2048L*EE];
__device__ __half g_Wvt[1024L*EE];
__device__ __half g_Wot[1024L*1024];
__device__ __half g_W1t[(long)FF*EE];
__device__ __half g_W2t[(long)EE*FF];
__device__ __half g_QKh[(long)NTOK*2048];
__device__ __half g_Vth[(long)BB*1024*SS];
__device__ __half g_att[268435456L];
__device__ float  g_part[64L*32*SS];
__device__ float  g_inv[(long)BB*HH*SS];
__device__ __half g_AVh[(long)NTOK*EE];
__device__ float  g_Y[(long)NTOK*EE];
__device__ float  g_VAf[(long)NTOK*EE];
__device__ __half g_VAh[(long)NTOK*EE];
__device__ __half g_H1h[(long)NTOK*FF];
__device__ float  g_Z[(long)NTOK*EE];

// ---------------- PTX helpers ----------------
__device__ __forceinline__ uint32_t smem_u32(const void* p) {
    uint32_t a;
    asm("{ .reg .u64 t; cvta.to.shared.u64 t, %1; cvt.u32.u64 %0, t; }" : "=r"(a) : "l"(p));
    return a;
}
__device__ __forceinline__ void cp16(uint32_t dst, const void* src) {
    asm volatile("cp.async.cg.shared.global [%0], [%1], 16;" :: "r"(dst), "l"(src));
}

// ---------------- HMMA f16 GEMM: C[M,N] = A[M,K] * B[N,K]^T ----------------
// BM=128, BK=64, 128 threads = 4 warps (2m x 2n), warp 64xWN.
// 3-stage cp.async pipeline; fragment double-buffering across ks steps.
template<int BN, bool OUT_HALF>
__global__ __launch_bounds__(128, 2)
void hgemm_kernel(const __half* __restrict__ A, const __half* __restrict__ B,
                  void* __restrict__ Cv, int K, int lda, int ldb, int ldc,
                  long sA1, long sA2, long sB1, long sB2, long sC1, long sC2, int Z2,
                  const float* __restrict__ bias, const float* __restrict__ residual,
                  int ldr, int do_relu, int do_exp, float* __restrict__ part)
{
    constexpr int BM = 128;
    constexpr int STG_A = BM * 128;
    constexpr int STG_B = BN * 128;
    constexpr int STG   = STG_A + STG_B;
    constexpr int WN = BN / 2;
    constexpr int MT = 4;
    constexpr int NT = WN / 8;

    extern __shared__ char smem_raw[];
    const uint32_t sb0   = smem_u32(smem_raw);
    const uint32_t sbase = (sb0 + 127u) & ~127u;

    const int tid  = threadIdx.x;
    const int lane = tid & 31;
    const int wid  = tid >> 5;
    const int wm   = (wid & 1) << 6;
    const int wn   = (wid >> 1) * WN;

    const int z  = blockIdx.z;
    const int z1 = z / Z2, z2 = z - z1 * Z2;
    A += z1 * sA1 + z2 * sA2;
    B += z1 * sB1 + z2 * sB2;
    const long coff = z1 * sC1 + z2 * sC2;
    const int m0 = blockIdx.y * BM;
    const int n0 = blockIdx.x * BN;

    float acc[MT][NT][4];
    #pragma unroll
    for (int i = 0; i < MT; i++)
        #pragma unroll
        for (int j = 0; j < NT; j++)
            #pragma unroll
            for (int k = 0; k < 4; k++) acc[i][j][k] = 0.0f;

    const int nK = K >> 6;

    auto load_stage = [&](int stg, int kt) {
        uint32_t sA = sbase + stg * STG;
        const char* Ab = (const char*)(A + (long)m0 * lda + kt * 64);
        #pragma unroll
        for (int idx = tid; idx < BM * 8; idx += 128) {
            int r = idx >> 3, c = (idx & 7) << 4;
            uint32_t off = (uint32_t)(r * 128 + c); off ^= (off >> 3) & 0x70;
            cp16(sA + off, Ab + (long)r * lda * 2 + c);
        }
        uint32_t sB = sbase + stg * STG + STG_A;
        const char* Bb = (const char*)(B + (long)n0 * ldb + kt * 64);
        #pragma unroll
        for (int idx = tid; idx < BN * 8; idx += 128) {
            int r = idx >> 3, c = (idx & 7) << 4;
            uint32_t off = (uint32_t)(r * 128 + c); off ^= (off >> 3) & 0x70;
            cp16(sB + off, Bb + (long)r * ldb * 2 + c);
        }
        asm volatile("cp.async.commit_group;" ::: "memory");
    };

    uint32_t afrag[2][MT][4];
    uint32_t bfrag[2][NT][2];
    auto load_afrags = [&](uint32_t sA, int ks, int buf) {
        #pragma unroll
        for (int mt = 0; mt < MT; mt++) {
            int m = wm + (mt << 4) + (lane & 15);
            uint32_t off = (uint32_t)((m << 7) + (ks << 5) + ((lane >> 4) << 4));
            off ^= (off >> 3) & 0x70;
            asm volatile("ldmatrix.sync.aligned.m8n8.x4.shared.b16 {%0,%1,%2,%3}, [%4];"
                : "=r"(afrag[buf][mt][0]), "=r"(afrag[buf][mt][1]),
                  "=r"(afrag[buf][mt][2]), "=r"(afrag[buf][mt][3])
                : "r"(sA + off));
        }
    };
    auto load_bfrags = [&](uint32_t sB, int ks, int buf) {
        #pragma unroll
        for (int p = 0; p < NT / 2; p++) {
            int quad = lane >> 3;
            int n = wn + (p << 4) + ((quad & 2) << 2) + (lane & 7);
            uint32_t off = (uint32_t)((n << 7) + (ks << 5) + ((quad & 1) << 4));
            off ^= (off >> 3) & 0x70;
            asm volatile("ldmatrix.sync.aligned.m8n8.x4.shared.b16 {%0,%1,%2,%3}, [%4];"
                : "=r"(bfrag[buf][2*p][0]), "=r"(bfrag[buf][2*p][1]),
                  "=r"(bfrag[buf][2*p+1][0]), "=r"(bfrag[buf][2*p+1][1])
                : "r"(sB + off));
        }
    };
    auto mma_all = [&](int buf) {
        #pragma unroll
        for (int mt = 0; mt < MT; mt++)
            #pragma unroll
            for (int nt = 0; nt < NT; nt++)
                asm("mma.sync.aligned.m16n8k16.row.col.f32.f16.f16.f32 "
                    "{%0,%1,%2,%3}, {%4,%5,%6,%7}, {%8,%9}, {%0,%1,%2,%3};"
                    : "+f"(acc[mt][nt][0]), "+f"(acc[mt][nt][1]),
                      "+f"(acc[mt][nt][2]), "+f"(acc[mt][nt][3])
                    : "r"(afrag[buf][mt][0]), "r"(afrag[buf][mt][1]),
                      "r"(afrag[buf][mt][2]), "r"(afrag[buf][mt][3]),
                      "r"(bfrag[buf][nt][0]), "r"(bfrag[buf][nt][1]));
    };

    load_stage(0, 0);
    if (nK > 1) load_stage(1, 1);

    for (int i = 0; i < nK; i++) {
        if (i + 1 < nK) asm volatile("cp.async.wait_group 1;" ::: "memory");
        else            asm volatile("cp.async.wait_group 0;" ::: "memory");
        __syncthreads();
        if (i + 2 < nK) load_stage((i + 2) % 3, i + 2);

        const uint32_t sA = sbase + (i % 3) * STG;
        const uint32_t sB = sA + STG_A;

        load_afrags(sA, 0, 0);
        load_bfrags(sB, 0, 0);
        #pragma unroll
        for (int ks = 0; ks < 4; ks++) {
            if (ks < 3) {
                load_afrags(sA, ks + 1, (ks + 1) & 1);
                load_bfrags(sB, ks + 1, (ks + 1) & 1);
            }
            mma_all(ks & 1);
        }
    }

    // -------- epilogue --------
    const int mrow = lane >> 2;
    const int ncol = (lane & 3) << 1;
    float cs[NT][2];
    #pragma unroll
    for (int j = 0; j < NT; j++) { cs[j][0] = 0.0f; cs[j][1] = 0.0f; }

    #pragma unroll
    for (int mt = 0; mt < MT; mt++) {
        #pragma unroll
        for (int nt = 0; nt < NT; nt++) {
            long gm = m0 + wm + (mt << 4) + mrow;
            int  gn = n0 + wn + (nt << 3) + ncol;
            float v0 = acc[mt][nt][0], v1 = acc[mt][nt][1];
            float v2 = acc[mt][nt][2], v3 = acc[mt][nt][3];
            if (bias) {
                float b0 = bias[gn], b1 = bias[gn + 1];
                v0 += b0; v1 += b1; v2 += b0; v3 += b1;
            }
            if (residual) {
                const float2 r0 = *(const float2*)(residual + gm * ldr + gn);
                const float2 r1 = *(const float2*)(residual + (gm + 8) * ldr + gn);
                v0 += r0.x; v1 += r0.y; v2 += r1.x; v3 += r1.y;
            }
            if (do_relu) {
                v0 = fmaxf(v0, 0.0f); v1 = fmaxf(v1, 0.0f);
                v2 = fmaxf(v2, 0.0f); v3 = fmaxf(v3, 0.0f);
            }
            if (do_exp) {
                v0 = fminf(__expf(v0 - EXP_SHIFT), 60000.0f);
                v1 = fminf(__expf(v1 - EXP_SHIFT), 60000.0f);
                v2 = fminf(__expf(v2 - EXP_SHIFT), 60000.0f);
                v3 = fminf(__expf(v3 - EXP_SHIFT), 60000.0f);
                cs[nt][0] += v0 + v2;
                cs[nt][1] += v1 + v3;
            }
            if (OUT_HALF) {
                *(__half2*)((__half*)Cv + coff + gm * ldc + gn)       = __floats2half2_rn(v0, v1);
                *(__half2*)((__half*)Cv + coff + (gm + 8) * ldc + gn) = __floats2half2_rn(v2, v3);
            } else {
                *(float2*)((float*)Cv + coff + gm * ldc + gn)       = make_float2(v0, v1);
                *(float2*)((float*)Cv + coff + (gm + 8) * ldc + gn) = make_float2(v2, v3);
            }
        }
    }

    if (do_exp) {
        #pragma unroll
        for (int nt = 0; nt < NT; nt++) {
            float c0 = cs[nt][0], c1 = cs[nt][1];
            #pragma unroll
            for (int o = 4; o <= 16; o <<= 1) {
                c0 += __shfl_xor_sync(0xffffffffu, c0, o);
                c1 += __shfl_xor_sync(0xffffffffu, c1, o);
            }
            if ((lane >> 2) == 0) {
                int gn = n0 + wn + (nt << 3) + ncol;
                long idx = (((long)z * gridDim.y + blockIdx.y) * 2 + (wid & 1)) * SS + gn;
                part[idx]     = c0;
                part[idx + 1] = c1;
            }
        }
    }
}

// ---------------- conversion / packing kernels ----------------
__global__ __launch_bounds__(256) void f2h_kernel(const float4* __restrict__ s,
                                                  __half2* __restrict__ d, long n4) {
    long i = (long)blockIdx.x * 256 + threadIdx.x;
    if (i < n4) {
        float4 v = s[i];
        d[i * 2]     = __floats2half2_rn(v.x, v.y);
        d[i * 2 + 1] = __floats2half2_rn(v.z, v.w);
    }
}
__global__ __launch_bounds__(256) void pack_w_kernel(const float* __restrict__ W,
                                                     __half* __restrict__ dst) {
    __shared__ float tile[32][33];
    int h  = blockIdx.z;
    int eb = blockIdx.y * 32, db = blockIdx.x * 32;
    const float* Wh = W + (long)h * EE * DD;
    #pragma unroll
    for (int dy = 0; dy < 32; dy += 8)
        tile[threadIdx.y + dy][threadIdx.x] =
            Wh[(long)(eb + threadIdx.y + dy) * DD + db + threadIdx.x];
    __syncthreads();
    #pragma unroll
    for (int dy = 0; dy < 32; dy += 8)
        dst[(long)(h * DD + db + threadIdx.y + dy) * EE + eb + threadIdx.x] =
            __float2half(tile[threadIdx.x][threadIdx.y + dy]);
}
__global__ __launch_bounds__(256) void transpose_h_kernel(const float* __restrict__ src,
                                                          __half* __restrict__ dst,
                                                          int R, int C) {
    __shared__ float tile[32][33];
    int rb = blockIdx.y * 32, cb = blockIdx.x * 32;
    #pragma unroll
    for (int dy = 0; dy < 32; dy += 8)
        tile[threadIdx.y + dy][threadIdx.x] =
            src[(long)(rb + threadIdx.y + dy) * C + cb + threadIdx.x];
    __syncthreads();
    #pragma unroll
    for (int dy = 0; dy < 32; dy += 8)
        dst[(long)(cb + threadIdx.y + dy) * R + rb + threadIdx.x] =
            __float2half(tile[threadIdx.x][threadIdx.y + dy]);
}

// ---------------- reduce partial col sums -> inv = 0.125/sum ----------------
__global__ __launch_bounds__(256) void reduce_inv_kernel(const float* __restrict__ part,
                                                         float* __restrict__ inv) {
    long z = blockIdx.y;
    int  t = blockIdx.x * 256 + threadIdx.x;
    const float* p = part + (z * 32) * (long)SS + t;
    float s = 0.0f;
    #pragma unroll
    for (int j = 0; j < 32; j++) s += p[(long)j * SS];
    inv[z * (long)SS + t] = 0.125f / s;
}

// ---------------- scale Vth rows by inv ----------------
__global__ __launch_bounds__(256) void vscale_kernel(__half* __restrict__ v,
                                                     const float* __restrict__ inv,
                                                     long nelem) {
    long i2 = (long)blockIdx.x * 256 + threadIdx.x;
    long i  = i2 * 2;
    if (i >= nelem) return;
    int t  = (int)(i & (SS - 1));
    int hd = (int)((i >> 11) & 1023);
    int b  = (int)(i >> 21);
    const float* ip = inv + ((long)(b * HH + (hd >> 6))) * SS + t;
    __half2* p = (__half2*)(v + i);
    float2 f = __half22float2(*p);
    f.x *= ip[0]; f.y *= ip[1];
    *p = __floats2half2_rn(f.x, f.y);
}

// ---------------- layernorm (E=1024), optional half copy ----------------
__global__ __launch_bounds__(256)
void layernorm_kernel(const float* __restrict__ x, const float* __restrict__ gamma,
                      const float* __restrict__ beta, float* __restrict__ outf,
                      __half* __restrict__ outh) {
    long row = blockIdx.x;
    const float* p = x + row * (long)EE;
    const int tid = threadIdx.x, lane = tid & 31, warp = tid >> 5;

    float v[4]; float s = 0.0f;
    #pragma unroll
    for (int i = 0; i < 4; i++) { v[i] = p[tid + i * 256]; s += v[i]; }
    __shared__ float red1[8], red2[8];
    #pragma unroll
    for (int o = 16; o > 0; o >>= 1) s += __shfl_xor_sync(0xffffffffu, s, o);
    if (lane == 0) red1[warp] = s;
    __syncthreads();
    float tot = red1[0];
    #pragma unroll
    for (int i = 1; i < 8; i++) tot += red1[i];
    float mu = tot * (1.0f / EE);

    float q = 0.0f;
    #pragma unroll
    for (int i = 0; i < 4; i++) { float d = v[i] - mu; q += d * d; }
    #pragma unroll
    for (int o = 16; o > 0; o >>= 1) q += __shfl_xor_sync(0xffffffffu, q, o);
    if (lane == 0) red2[warp] = q;
    __syncthreads();
    float qt = red2[0];
    #pragma unroll
    for (int i = 1; i < 8; i++) qt += red2[i];
    float rstd = rsqrtf(qt * (1.0f / EE) + LN_EPS);

    #pragma unroll
    for (int i = 0; i < 4; i++) {
        int col = tid + i * 256;
        float y = (v[i] - mu) * rstd * gamma[col] + beta[col];
        outf[row * (long)EE + col] = y;
        if (outh) outh[row * (long)EE + col] = __float2half(y);
    }
}

// ---------------- launcher ----------------
extern "C" void kernel_launch(void* const* d_in, const int* in_sizes, int n_in,
                              void* d_out, int out_size)
{
    const float* X     = (const float*)d_in[0];
    const float* WQ    = (const float*)d_in[1];
    const float* WK    = (const float*)d_in[2];
    const float* WV    = (const float*)d_in[3];
    const float* WO    = (const float*)d_in[4];
    const float* gamma = (const float*)d_in[5];
    const float* beta  = (const float*)d_in[6];
    const float* W1    = (const float*)d_in[7];
    const float* b1    = (const float*)d_in[8];
    const float* W2    = (const float*)d_in[9];
    const float* b2    = (const float*)d_in[10];
    float* out = (float*)d_out;

    __half *Xh, *Wqk, *Wvt, *Wot, *W1t, *W2t, *QKh, *Vth, *ATT, *AVh, *VAh, *H1h;
    float *PART, *INV, *Y, *VAf, *Z;
    cudaGetSymbolAddress((void**)&Xh,  g_Xh);
    cudaGetSymbolAddress((void**)&Wqk, g_Wqk);
    cudaGetSymbolAddress((void**)&Wvt, g_Wvt);
    cudaGetSymbolAddress((void**)&Wot, g_Wot);
    cudaGetSymbolAddress((void**)&W1t, g_W1t);
    cudaGetSymbolAddress((void**)&W2t, g_W2t);
    cudaGetSymbolAddress((void**)&QKh, g_QKh);
    cudaGetSymbolAddress((void**)&Vth, g_Vth);
    cudaGetSymbolAddress((void**)&ATT, g_att);
    cudaGetSymbolAddress((void**)&PART, g_part);
    cudaGetSymbolAddress((void**)&INV, g_inv);
    cudaGetSymbolAddress((void**)&AVh, g_AVh);
    cudaGetSymbolAddress((void**)&Y,   g_Y);
    cudaGetSymbolAddress((void**)&VAf, g_VAf);
    cudaGetSymbolAddress((void**)&VAh, g_VAh);
    cudaGetSymbolAddress((void**)&H1h, g_H1h);
    cudaGetSymbolAddress((void**)&Z,   g_Z);

    static cudaStream_t sW = nullptr, sH[2] = {nullptr, nullptr};
    static cudaEvent_t evFork = nullptr, evW = nullptr, evD0 = nullptr, evD1 = nullptr;
    if (!sW) {
        int pl, pg;
        cudaDeviceGetStreamPriorityRange(&pl, &pg);
        cudaStreamCreateWithFlags(&sW, cudaStreamNonBlocking);
        cudaStreamCreateWithPriority(&sH[0], cudaStreamNonBlocking, pg);   // high prio
        cudaStreamCreateWithPriority(&sH[1], cudaStreamNonBlocking, pl);   // low prio
        cudaEventCreateWithFlags(&evFork, cudaEventDisableTiming);
        cudaEventCreateWithFlags(&evW,    cudaEventDisableTiming);
        cudaEventCreateWithFlags(&evD0,   cudaEventDisableTiming);
        cudaEventCreateWithFlags(&evD1,   cudaEventDisableTiming);
    }

    const int SM128 = 3 * (128 * 128 + 128 * 128) + 256;
    const int SM64  = 3 * (128 * 128 +  64 * 128) + 256;
    cudaFuncSetAttribute(hgemm_kernel<128, true>,  cudaFuncAttributeMaxDynamicSharedMemorySize, SM128);
    cudaFuncSetAttribute(hgemm_kernel<128, false>, cudaFuncAttributeMaxDynamicSharedMemorySize, SM128);
    cudaFuncSetAttribute(hgemm_kernel<64,  true>,  cudaFuncAttributeMaxDynamicSharedMemorySize, SM64);

    const long SSl = SS, SSS = SSl * SSl;
    dim3 blk(256);
    dim3 gblk(128);
    dim3 tblk(32, 8);

    // ---- stream 0: shared prep (Xh + QK weight pack), then fork ----
    f2h_kernel<<<(NTOK * (long)EE / 4 + 255) / 256, blk>>>(
        (const float4*)X, (__half2*)Xh, NTOK * (long)EE / 4);
    pack_w_kernel<<<dim3(2, 32, HH), tblk>>>(WQ, Wqk);
    pack_w_kernel<<<dim3(2, 32, HH), tblk>>>(WK, Wqk + 1024L * EE);
    cudaEventRecord(evFork, 0);

    // ---- weight stream: V/O/FFN weight packs (independent of X) ----
    cudaStreamWaitEvent(sW, evFork, 0);
    pack_w_kernel<<<dim3(2, 32, HH), tblk, 0, sW>>>(WV, Wvt);
    transpose_h_kernel<<<dim3(1024 / 32, 1024 / 32), tblk, 0, sW>>>(WO, Wot, 1024, 1024);
    transpose_h_kernel<<<dim3(FF / 32, EE / 32), tblk, 0, sW>>>(W1, W1t, EE, FF);
    transpose_h_kernel<<<dim3(EE / 32, FF / 32), tblk, 0, sW>>>(W2, W2t, FF, EE);
    cudaEventRecord(evW, sW);

    // ---- per-half pipelines (h = 0: batches 0-1, h = 1: batches 2-3) ----
    for (int h = 0; h < 2; h++) {
        cudaStream_t s = sH[h];
        cudaStreamWaitEvent(s, evFork, 0);
        cudaStreamWaitEvent(s, evW, 0);

        const long xOff   = (long)h * HTOK * EE;       // tokens (fp32/half X, AV, Y, VA, Z, out)
        const long qkOff  = (long)h * HTOK * 2048;
        const long vtOff  = (long)h * 2 * 1024L * SS;
        const long attOff = (long)h * 32L * SSS;
        const long partOff= (long)h * 32L * 32 * SS;
        const long invOff = (long)h * 32L * SS;
        const long h1Off  = (long)h * HTOK * (long)FF;

        // 1) QK projection half: [4096,1024] x [2048,1024]^T -> QKh
        hgemm_kernel<128, true><<<dim3(2048 / 128, HTOK / 128, 1), gblk, SM128, s>>>(
            Xh + xOff, Wqk, QKh + qkOff, EE, EE, EE, 2048,
            0, 0, 0, 0, 0, 0, 1, nullptr, nullptr, 0, 0, 0, nullptr);

        // 2) Vt half: per b: Wvt [1024,1024] x Xh_b^T -> Vth[b][1024,2048]
        hgemm_kernel<128, true><<<dim3(SS / 128, 1024 / 128, 2), gblk, SM128, s>>>(
            Wvt, Xh + xOff, Vth + vtOff, EE, EE, EE, SS,
            0, 0, (long)SS * EE, 0, 1024L * SS, 0, 1, nullptr, nullptr, 0, 0, 0, nullptr);

        // 3) scores + exp + partial col sums (32 z per half)
        hgemm_kernel<128, true><<<dim3(SS / 128, SS / 128, 2 * HH), gblk, SM128, s>>>(
            QKh + qkOff, QKh + qkOff + 1024, ATT + attOff, DD, 2048, 2048, SS,
            SSl * 2048, 64, SSl * 2048, 64, (long)HH * SSS, SSS, HH,
            nullptr, nullptr, 0, 0, 1, PART + partOff);

        // 4) reduce partials -> inv; fold into V
        reduce_inv_kernel<<<dim3(SS / 256, 2 * HH), blk, 0, s>>>(PART + partOff, INV + invOff);
        vscale_kernel<<<(int)((2 * 1024L * SS / 2 + 255) / 256), blk, 0, s>>>(
            Vth + vtOff, INV + invOff, 2 * 1024L * SS);

        // 5) AV half
        hgemm_kernel<64, true><<<dim3(1, SS / 128, 2 * HH), gblk, SM64, s>>>(
            ATT + attOff, Vth + vtOff, AVh + xOff, SS, SS, SS, EE,
            (long)HH * SSS, SSS, 1024L * SS, 64L * SS, SSl * EE, 64, HH,
            nullptr, nullptr, 0, 0, 0, nullptr);

        // 6) WO + residual X; LN -> VAf/VAh
        hgemm_kernel<128, false><<<dim3(EE / 128, HTOK / 128, 1), gblk, SM128, s>>>(
            AVh + xOff, Wot, Y + xOff, 1024, 1024, 1024, EE,
            0, 0, 0, 0, 0, 0, 1, nullptr, X + xOff, EE, 0, 0, nullptr);
        layernorm_kernel<<<HTOK, blk, 0, s>>>(Y + xOff, gamma, beta, VAf + xOff, VAh + xOff);

        // 7) FFN1
        hgemm_kernel<128, true><<<dim3(FF / 128, HTOK / 128, 1), gblk, SM128, s>>>(
            VAh + xOff, W1t, H1h + h1Off, EE, EE, EE, FF,
            0, 0, 0, 0, 0, 0, 1, b1, nullptr, 0, 1, 0, nullptr);

        // 8) FFN2 + residual VAf; LN -> out
        hgemm_kernel<128, false><<<dim3(EE / 128, HTOK / 128, 1), gblk, SM128, s>>>(
            H1h + h1Off, W2t, Z + xOff, FF, FF, FF, EE,
            0, 0, 0, 0, 0, 0, 1, b2, VAf + xOff, EE, 0, 0, nullptr);
        layernorm_kernel<<<HTOK, blk, 0, s>>>(Z + xOff, gamma, beta, out + xOff, nullptr);

        cudaEventRecord(h == 0 ? evD0 : evD1, s);
    }

    // ---- join back to capture stream ----
    cudaStreamWaitEvent(0, evD0, 0);
    cudaStreamWaitEvent(0, evD1, 0);
}